// round 13
// baseline (speedup 1.0000x reference)
#include <cuda_runtime.h>

#define C_NUM   19
#define DIM     128
#define STRIPES 4
#define SW      32                 // stripe width (floats)
#define WPB     8
#define TPB     256
#define BPS     6                  // blocks per SM
#define GRID    (148 * BPS)        // 888 = single full wave (residency guaranteed)
#define U1      8                  // phase-1 row unroll
#define U2      4                  // phase-2 row unroll
#define NW1     (GRID / STRIPES * WPB)   // 1776 warps per stripe
#define NW2     (GRID * WPB)             // 7104 warps in phase 2

// Persistent scratch. Zero-initialized on load; the LAST exiting block resets
// everything at the end of each run, so every graph replay starts from zeros.
__device__ float    g_sums[C_NUM * DIM];
__device__ float    g_counts[C_NUM];
__device__ float    g_loss;
__device__ unsigned g_arrive;
__device__ unsigned g_exit;
__device__ volatile int g_release;

__device__ __forceinline__ int clamp_c(int t) {
    return t < 0 ? 0 : (t >= C_NUM ? C_NUM - 1 : t);
}

__global__ __launch_bounds__(TPB, BPS)
void fused_kernel(const float* __restrict__ x,
                  const int*   __restrict__ t32,
                  float* __restrict__ out, int n) {
    __shared__ union {
        float acc[WPB][C_NUM * SW];     // phase 1: per-warp private accumulators (19,456 B)
        float ctr[C_NUM * DIM];         // phase 2: centers (9,728 B)
    } sm;
    __shared__ int   cnt[WPB][C_NUM];
    __shared__ float wsum[WPB];
    __shared__ int   s_misc[2];          // [0]=tmode shift, [1]=last-block flag

    const int tid  = threadIdx.x;
    const int warp = tid >> 5;
    const int lane = tid & 31;

    // ---- dtype probe (int64 labels in [0,19) -> odd 32-bit words all zero) ----
    if (warp == 0) {
        int m = n < 128 ? n : 128;
        int oddnz = 0;
        for (int i = lane; i < m; i += 32)
            if (t32[2 * i + 1] != 0) oddnz = 1;
        unsigned any = __ballot_sync(0xffffffffu, oddnz);
        if (lane == 0) s_misc[0] = (any == 0u) ? 1 : 0;
    }

    // ---- zero phase-1 accumulators ----
    for (int e = tid; e < WPB * C_NUM * SW; e += TPB) (&sm.acc[0][0])[e] = 0.f;
    for (int e = tid; e < WPB * C_NUM; e += TPB) (&cnt[0][0])[e] = 0;
    __syncthreads();
    const int sh = s_misc[0];

    // =========================== PHASE 1: striped segment sums ===========================
    // Block owns stripe `sid` (32 floats of the feature dim) for a contiguous row chunk.
    // Warp-instruction loads 128 contiguous bytes (one L2 line, fetched once chip-wide).
    // Per-warp private accumulator -> no hot-loop atomics; lane l -> bank l, conflict-free.
    {
        const int sid  = blockIdx.x & (STRIPES - 1);
        const int ws   = (blockIdx.x >> 2) * WPB + warp;      // warp id within stripe
        const int rpw  = (n + NW1 - 1) / NW1;                 // rows per warp (contiguous)
        const int base = ws * rpw;
        const int end  = (base + rpw) < n ? (base + rpw) : n;
        const int off  = sid * SW + lane;
        float* my = sm.acc[warp];

        for (int r = base; r < end; r += U1) {
            int   t[U1];
            float v[U1];
            bool  ok[U1];
            #pragma unroll
            for (int u = 0; u < U1; u++) {                    // front-batched loads (MLP)
                int ri = r + u;
                ok[u] = ri < end;
                if (ok[u]) {
                    t[u] = clamp_c(t32[ri << sh]);            // scalar, warp-broadcast
                    v[u] = x[ri * DIM + off];
                }
            }
            #pragma unroll
            for (int u = 0; u < U1; u++) {
                if (ok[u]) {
                    my[t[u] * SW + lane] += v[u];
                    if (lane == 0 && sid == 0) cnt[warp][t[u]]++;
                }
            }
        }
        __syncthreads();

        // block-reduce 8 warp accumulators, flush to global (608 floats/block via L2 atomics)
        const int gbase = sid * SW;
        for (int e = tid; e < C_NUM * SW; e += TPB) {
            float s = 0.f;
            #pragma unroll
            for (int w = 0; w < WPB; w++) s += sm.acc[w][e];
            int c = e >> 5, j = e & 31;
            atomicAdd(&g_sums[c * DIM + gbase + j], s);
        }
        if (sid == 0) {
            for (int e = tid; e < C_NUM; e += TPB) {
                int s = 0;
                #pragma unroll
                for (int w = 0; w < WPB; w++) s += cnt[w][e];
                atomicAdd(&g_counts[e], (float)s);
            }
        }
    }

    // =========================== grid-wide barrier ===========================
    __threadfence();
    __syncthreads();
    if (tid == 0) {
        unsigned old = atomicAdd(&g_arrive, 1u);
        if (old == GRID - 1) { __threadfence(); g_release = 1; }
        else { while (g_release == 0) { } }
    }
    __syncthreads();

    // =========================== PHASE 2: distances ===========================
    // Centers from global (L2 reads, post-barrier). Reverse row traversal.
    for (int e = tid; e < C_NUM * DIM; e += TPB)
        sm.ctr[e] = __ldcg(&g_sums[e]) / __ldcg(&g_counts[e >> 7]);
    __syncthreads();

    {
        const float* ctr = sm.ctr;
        const int gw = blockIdx.x * WPB + warp;
        const float4* x4 = (const float4*)x;
        float lsum = 0.f;

        for (int r = gw; r < n; r += U2 * NW2) {
            const int rv0 = n - 1 - r;
            const int rv1 = rv0 - NW2, rv2 = rv0 - 2 * NW2, rv3 = rv0 - 3 * NW2;
            const bool ok1 = (r + NW2) < n, ok2 = (r + 2 * NW2) < n, ok3 = (r + 3 * NW2) < n;

            int t0, t1 = 0, t2 = 0, t3 = 0;
            float4 v0, v1, v2, v3;
            t0 = clamp_c(t32[rv0 << sh]); v0 = x4[rv0 * 32 + lane];
            if (ok1) { t1 = clamp_c(t32[rv1 << sh]); v1 = x4[rv1 * 32 + lane]; }
            if (ok2) { t2 = clamp_c(t32[rv2 << sh]); v2 = x4[rv2 * 32 + lane]; }
            if (ok3) { t3 = clamp_c(t32[rv3 << sh]); v3 = x4[rv3 * 32 + lane]; }

            float s0, s1 = 0.f, s2 = 0.f, s3 = 0.f;
            {
                float4 c = ((const float4*)(ctr + t0 * DIM))[lane];
                float dx = v0.x - c.x, dy = v0.y - c.y, dz = v0.z - c.z, dw = v0.w - c.w;
                s0 = dx * dx + dy * dy + dz * dz + dw * dw;
            }
            if (ok1) {
                float4 c = ((const float4*)(ctr + t1 * DIM))[lane];
                float dx = v1.x - c.x, dy = v1.y - c.y, dz = v1.z - c.z, dw = v1.w - c.w;
                s1 = dx * dx + dy * dy + dz * dz + dw * dw;
            }
            if (ok2) {
                float4 c = ((const float4*)(ctr + t2 * DIM))[lane];
                float dx = v2.x - c.x, dy = v2.y - c.y, dz = v2.z - c.z, dw = v2.w - c.w;
                s2 = dx * dx + dy * dy + dz * dz + dw * dw;
            }
            if (ok3) {
                float4 c = ((const float4*)(ctr + t3 * DIM))[lane];
                float dx = v3.x - c.x, dy = v3.y - c.y, dz = v3.z - c.z, dw = v3.w - c.w;
                s3 = dx * dx + dy * dy + dz * dz + dw * dw;
            }

            #pragma unroll
            for (int off = 16; off > 0; off >>= 1) {
                s0 += __shfl_xor_sync(0xffffffffu, s0, off);
                s1 += __shfl_xor_sync(0xffffffffu, s1, off);
                s2 += __shfl_xor_sync(0xffffffffu, s2, off);
                s3 += __shfl_xor_sync(0xffffffffu, s3, off);
            }
            if (lane == 0) {
                lsum += sqrtf(s0);
                if (ok1) lsum += sqrtf(s1);
                if (ok2) lsum += sqrtf(s2);
                if (ok3) lsum += sqrtf(s3);
            }
        }

        if (lane == 0) wsum[warp] = lsum;
        __syncthreads();
        if (tid == 0) {
            float s = 0.f;
            #pragma unroll
            for (int w = 0; w < WPB; w++) s += wsum[w];
            atomicAdd(&g_loss, s);
        }
    }

    // =========================== finalize + reset (last block) ===========================
    __threadfence();
    __syncthreads();
    if (tid == 0) {
        unsigned old = atomicAdd(&g_exit, 1u);
        s_misc[1] = (old == GRID - 1) ? 1 : 0;
    }
    __syncthreads();
    if (s_misc[1]) {
        // all other blocks have added to g_loss (fence + L2 atomic ordering)
        if (tid == 0) {
            __threadfence();
            float total = atomicAdd(&g_loss, 0.f);
            out[0] = total / (float)n;
        }
        // reset scratch for the next (deterministic) replay
        for (int e = tid; e < C_NUM * DIM; e += TPB) g_sums[e] = 0.f;
        if (tid < C_NUM) g_counts[tid] = 0.f;
        __syncthreads();
        if (tid == 0) {
            g_loss = 0.f;
            g_arrive = 0u;
            g_exit = 0u;
            __threadfence();
            g_release = 0;
        }
    }
}

// ---------------------------------------------------------------- launch
extern "C" void kernel_launch(void* const* d_in, const int* in_sizes, int n_in,
                              void* d_out, int out_size) {
    // Resolve input ordering by element count: inputs has 128x the elements of targets.
    const void* a = d_in[0];
    const void* b = d_in[1];
    const float* x;
    const int*   tgt;
    int n;
    if (in_sizes[0] >= in_sizes[1]) {
        x = (const float*)a;  tgt = (const int*)b;  n = in_sizes[1];
    } else {
        x = (const float*)b;  tgt = (const int*)a;  n = in_sizes[0];
    }
    float* out = (float*)d_out;

    fused_kernel<<<GRID, TPB>>>(x, tgt, out, n);
}

// round 14
// speedup vs baseline: 1.0153x; 1.0153x over previous
#include <cuda_runtime.h>

#define C_NUM   19
#define DIM     128
#define STRIPES 4
#define SW      32                 // stripe width (floats)
#define WPB     8
#define TPB     256
#define BPS     6                  // blocks per SM
#define GRID    (148 * BPS)        // 888 = single full wave (residency guaranteed)
#define U1      8                  // phase-1 row unroll
#define U2      4                  // phase-2 row unroll
#define NW1     (GRID / STRIPES * WPB)   // 1776 warps per stripe
#define NW2     (GRID * WPB)             // 7104 warps in phase 2

// Persistent scratch. Zero-initialized on load; the LAST exiting block resets
// everything at the end of each run, so every graph replay starts from zeros.
__device__ float    g_sums[C_NUM * DIM];
__device__ float    g_counts[C_NUM];
__device__ float    g_loss;
__device__ unsigned g_arrive;
__device__ unsigned g_exit;
__device__ volatile int g_release;

__device__ __forceinline__ int clamp_c(int t) {
    return t < 0 ? 0 : (t >= C_NUM ? C_NUM - 1 : t);
}

__global__ __launch_bounds__(TPB, BPS)
void fused_kernel(const float* __restrict__ x,
                  const int*   __restrict__ t32,
                  float* __restrict__ out, int n) {
    __shared__ union {
        float acc[WPB][C_NUM * SW];     // phase 1: per-warp private accumulators (19,456 B)
        float ctr[C_NUM * DIM];         // phase 2: centers (9,728 B)
    } sm;
    __shared__ int   cnt[WPB][C_NUM];
    __shared__ float wsum[WPB];
    __shared__ int   s_misc[2];          // [0]=tmode shift, [1]=last-block flag

    const int tid  = threadIdx.x;
    const int warp = tid >> 5;
    const int lane = tid & 31;

    // ---- dtype probe (int64 labels in [0,19) -> odd 32-bit words all zero) ----
    if (warp == 0) {
        int m = n < 128 ? n : 128;
        int oddnz = 0;
        for (int i = lane; i < m; i += 32)
            if (t32[2 * i + 1] != 0) oddnz = 1;
        unsigned any = __ballot_sync(0xffffffffu, oddnz);
        if (lane == 0) s_misc[0] = (any == 0u) ? 1 : 0;
    }

    // ---- zero phase-1 accumulators ----
    for (int e = tid; e < WPB * C_NUM * SW; e += TPB) (&sm.acc[0][0])[e] = 0.f;
    for (int e = tid; e < WPB * C_NUM; e += TPB) (&cnt[0][0])[e] = 0;
    __syncthreads();
    const int sh = s_misc[0];

    // =========================== PHASE 1: striped segment sums ===========================
    // Block owns stripe `sid` (32 floats of the feature dim) for a contiguous row chunk.
    // Warp-instruction loads 128 contiguous bytes (one L2 line, fetched once chip-wide).
    // Per-warp private accumulator -> no hot-loop atomics; lane l -> bank l, conflict-free.
    {
        const int sid  = blockIdx.x & (STRIPES - 1);
        const int ws   = (blockIdx.x >> 2) * WPB + warp;      // warp id within stripe
        const int rpw  = (n + NW1 - 1) / NW1;                 // rows per warp (contiguous)
        const int base = ws * rpw;
        const int end  = (base + rpw) < n ? (base + rpw) : n;
        const int off  = sid * SW + lane;
        float* my = sm.acc[warp];

        for (int r = base; r < end; r += U1) {
            int   t[U1];
            float v[U1];
            bool  ok[U1];
            #pragma unroll
            for (int u = 0; u < U1; u++) {                    // front-batched loads (MLP)
                int ri = r + u;
                ok[u] = ri < end;
                if (ok[u]) {
                    t[u] = clamp_c(t32[ri << sh]);            // scalar, warp-broadcast
                    v[u] = x[ri * DIM + off];
                }
            }
            #pragma unroll
            for (int u = 0; u < U1; u++) {
                if (ok[u]) {
                    my[t[u] * SW + lane] += v[u];
                    if (lane == 0 && sid == 0) cnt[warp][t[u]]++;
                }
            }
        }
        __syncthreads();

        // block-reduce 8 warp accumulators, flush to global (608 floats/block via L2 atomics)
        const int gbase = sid * SW;
        for (int e = tid; e < C_NUM * SW; e += TPB) {
            float s = 0.f;
            #pragma unroll
            for (int w = 0; w < WPB; w++) s += sm.acc[w][e];
            int c = e >> 5, j = e & 31;
            atomicAdd(&g_sums[c * DIM + gbase + j], s);
        }
        if (sid == 0) {
            for (int e = tid; e < C_NUM; e += TPB) {
                int s = 0;
                #pragma unroll
                for (int w = 0; w < WPB; w++) s += cnt[w][e];
                atomicAdd(&g_counts[e], (float)s);
            }
        }
    }

    // =========================== grid-wide barrier ===========================
    __threadfence();
    __syncthreads();
    if (tid == 0) {
        unsigned old = atomicAdd(&g_arrive, 1u);
        if (old == GRID - 1) { __threadfence(); g_release = 1; }
        else { while (g_release == 0) { } }
    }
    __syncthreads();

    // =========================== PHASE 2: distances ===========================
    // Centers from global (L2 reads, post-barrier). Reverse row traversal.
    for (int e = tid; e < C_NUM * DIM; e += TPB)
        sm.ctr[e] = __ldcg(&g_sums[e]) / __ldcg(&g_counts[e >> 7]);
    __syncthreads();

    {
        const float* ctr = sm.ctr;
        const int gw = blockIdx.x * WPB + warp;
        const float4* x4 = (const float4*)x;
        float lsum = 0.f;

        for (int r = gw; r < n; r += U2 * NW2) {
            const int rv0 = n - 1 - r;
            const int rv1 = rv0 - NW2, rv2 = rv0 - 2 * NW2, rv3 = rv0 - 3 * NW2;
            const bool ok1 = (r + NW2) < n, ok2 = (r + 2 * NW2) < n, ok3 = (r + 3 * NW2) < n;

            int t0, t1 = 0, t2 = 0, t3 = 0;
            float4 v0, v1, v2, v3;
            t0 = clamp_c(t32[rv0 << sh]); v0 = x4[rv0 * 32 + lane];
            if (ok1) { t1 = clamp_c(t32[rv1 << sh]); v1 = x4[rv1 * 32 + lane]; }
            if (ok2) { t2 = clamp_c(t32[rv2 << sh]); v2 = x4[rv2 * 32 + lane]; }
            if (ok3) { t3 = clamp_c(t32[rv3 << sh]); v3 = x4[rv3 * 32 + lane]; }

            float s0, s1 = 0.f, s2 = 0.f, s3 = 0.f;
            {
                float4 c = ((const float4*)(ctr + t0 * DIM))[lane];
                float dx = v0.x - c.x, dy = v0.y - c.y, dz = v0.z - c.z, dw = v0.w - c.w;
                s0 = dx * dx + dy * dy + dz * dz + dw * dw;
            }
            if (ok1) {
                float4 c = ((const float4*)(ctr + t1 * DIM))[lane];
                float dx = v1.x - c.x, dy = v1.y - c.y, dz = v1.z - c.z, dw = v1.w - c.w;
                s1 = dx * dx + dy * dy + dz * dz + dw * dw;
            }
            if (ok2) {
                float4 c = ((const float4*)(ctr + t2 * DIM))[lane];
                float dx = v2.x - c.x, dy = v2.y - c.y, dz = v2.z - c.z, dw = v2.w - c.w;
                s2 = dx * dx + dy * dy + dz * dz + dw * dw;
            }
            if (ok3) {
                float4 c = ((const float4*)(ctr + t3 * DIM))[lane];
                float dx = v3.x - c.x, dy = v3.y - c.y, dz = v3.z - c.z, dw = v3.w - c.w;
                s3 = dx * dx + dy * dy + dz * dz + dw * dw;
            }

            #pragma unroll
            for (int off = 16; off > 0; off >>= 1) {
                s0 += __shfl_xor_sync(0xffffffffu, s0, off);
                s1 += __shfl_xor_sync(0xffffffffu, s1, off);
                s2 += __shfl_xor_sync(0xffffffffu, s2, off);
                s3 += __shfl_xor_sync(0xffffffffu, s3, off);
            }
            if (lane == 0) {
                lsum += sqrtf(s0);
                if (ok1) lsum += sqrtf(s1);
                if (ok2) lsum += sqrtf(s2);
                if (ok3) lsum += sqrtf(s3);
            }
        }

        if (lane == 0) wsum[warp] = lsum;
        __syncthreads();
        if (tid == 0) {
            float s = 0.f;
            #pragma unroll
            for (int w = 0; w < WPB; w++) s += wsum[w];
            atomicAdd(&g_loss, s);
        }
    }

    // =========================== finalize + reset (last block) ===========================
    __threadfence();
    __syncthreads();
    if (tid == 0) {
        unsigned old = atomicAdd(&g_exit, 1u);
        s_misc[1] = (old == GRID - 1) ? 1 : 0;
    }
    __syncthreads();
    if (s_misc[1]) {
        // all other blocks have added to g_loss (fence + L2 atomic ordering)
        if (tid == 0) {
            __threadfence();
            float total = atomicAdd(&g_loss, 0.f);
            out[0] = total / (float)n;
        }
        // reset scratch for the next (deterministic) replay
        for (int e = tid; e < C_NUM * DIM; e += TPB) g_sums[e] = 0.f;
        if (tid < C_NUM) g_counts[tid] = 0.f;
        __syncthreads();
        if (tid == 0) {
            g_loss = 0.f;
            g_arrive = 0u;
            g_exit = 0u;
            __threadfence();
            g_release = 0;
        }
    }
}

// ---------------------------------------------------------------- launch
extern "C" void kernel_launch(void* const* d_in, const int* in_sizes, int n_in,
                              void* d_out, int out_size) {
    // Resolve input ordering by element count: inputs has 128x the elements of targets.
    const void* a = d_in[0];
    const void* b = d_in[1];
    const float* x;
    const int*   tgt;
    int n;
    if (in_sizes[0] >= in_sizes[1]) {
        x = (const float*)a;  tgt = (const int*)b;  n = in_sizes[1];
    } else {
        x = (const float*)b;  tgt = (const int*)a;  n = in_sizes[0];
    }
    float* out = (float*)d_out;

    fused_kernel<<<GRID, TPB>>>(x, tgt, out, n);
}

// round 15
// speedup vs baseline: 1.2743x; 1.2551x over previous
#include <cuda_runtime.h>

#define C_NUM 19
#define DIM   128

// ---- k1: warp-pair feature split. 8 warps/block, 4.86KB acc/warp -> 38.9KB/block
//      -> 5 blocks/SM -> 40 warps/SM (2x the old k1 occupancy), LDG.64 loads.
#define K1_WPB   8
#define K1_TPB   (K1_WPB * 32)
#define K1_GRID  740                   // 5 blocks/SM * 148 SMs -> single wave
#define K1_PAIRS (K1_GRID * (K1_WPB / 2))   // 2960 warp-pairs
#define U1       8

// ---- k2: unchanged from round 12 (known good) ----
#define K2_WPB   8
#define K2_TPB   (K2_WPB * 32)
#define K2_GRID  888                   // 6 blocks/SM; 48 warps/SM

__device__ float g_sums[C_NUM * DIM];
__device__ float g_counts[C_NUM];
__device__ float g_loss;
__device__ int   g_tmode;              // 0 = targets int32[n], 1 = targets int64[n]

// ---------------------------------------------------------------- k0: zero + dtype probe
__global__ void k0_zero_probe(const int* __restrict__ t32, int n) {
    int tid = threadIdx.x;
    for (int e = tid; e < C_NUM * DIM; e += blockDim.x) g_sums[e] = 0.f;
    if (tid < C_NUM) g_counts[tid] = 0.f;
    if (tid == 0) g_loss = 0.f;

    if (tid < 32) {
        // int64 labels in [0,19) -> every odd 32-bit word is 0 (LE high word).
        int m = n < 128 ? n : 128;
        int oddnz = 0;
        for (int i = tid; i < m; i += 32)
            if (t32[2 * i + 1] != 0) oddnz = 1;
        unsigned any = __ballot_sync(0xffffffffu, oddnz);
        if (tid == 0) g_tmode = (any == 0u) ? 1 : 0;
    }
}

__device__ __forceinline__ int load_tgt(const int* __restrict__ t32, int r, int sh) {
    int t = t32[r << sh];                      // sh=1: int64 low word; sh=0: int32
    return t < 0 ? 0 : (t >= C_NUM ? C_NUM - 1 : t);
}

// ---------------------------------------------------------------- k1: per-class sums
// Warp pair splits each 512B row: even warp owns cols [0,64), odd warp cols [64,128).
// Each warp: LDG.64 per half-row (256B, coalesced; the pair consumes the full L2 line),
// private [19][64] shared accumulator -> conflict-free LDS.64/STS.64 RMW, no atomics.
// 8 half-rows unrolled, loads front-batched for MLP.
__global__ __launch_bounds__(K1_TPB) void k1_segsum(const float2* __restrict__ x2,
                                                    const int* __restrict__ t32,
                                                    int n) {
    __shared__ __align__(16) float acc[K1_WPB][C_NUM * 64];   // 38,912 B
    __shared__ int cnt[K1_WPB][C_NUM];

    const int tid  = threadIdx.x;
    const int warp = tid >> 5;
    const int lane = tid & 31;
    const int sh   = g_tmode;

    for (int e = tid; e < K1_WPB * C_NUM * 64; e += K1_TPB) (&acc[0][0])[e] = 0.f;
    for (int e = tid; e < K1_WPB * C_NUM; e += K1_TPB) (&cnt[0][0])[e] = 0;
    __syncthreads();

    const int pair = blockIdx.x * (K1_WPB / 2) + (warp >> 1);
    const int half = warp & 1;
    const int col  = half * 32 + lane;        // float2 index within the 64-float2 row
    float* my = acc[warp];

    for (int r = pair; r < n; r += U1 * K1_PAIRS) {
        int    t[U1];
        float2 v[U1];
        bool   ok[U1];
        #pragma unroll
        for (int u = 0; u < U1; u++) {        // front-batched global loads (MLP)
            int ri = r + u * K1_PAIRS;
            ok[u] = ri < n;
            if (ok[u]) {
                t[u] = load_tgt(t32, ri, sh); // scalar, L1-broadcast within pair
                v[u] = x2[ri * 64 + col];
            }
        }
        #pragma unroll
        for (int u = 0; u < U1; u++) {
            if (ok[u]) {
                float2* p = (float2*)(my + t[u] * 64) + lane;
                float2 a = *p;
                a.x += v[u].x; a.y += v[u].y;
                *p = a;
                if (half == 0 && lane == 0) cnt[warp][t[u]]++;
            }
        }
    }
    __syncthreads();

    // block-reduce: 4 even-warp accumulators -> cols [0,64), 4 odd -> cols [64,128)
    for (int e = tid; e < C_NUM * 64; e += K1_TPB) {
        int c = e >> 6, j = e & 63;
        float s0 = acc[0][e] + acc[2][e] + acc[4][e] + acc[6][e];
        float s1 = acc[1][e] + acc[3][e] + acc[5][e] + acc[7][e];
        atomicAdd(&g_sums[c * DIM + j], s0);
        atomicAdd(&g_sums[c * DIM + 64 + j], s1);
    }
    for (int e = tid; e < C_NUM; e += K1_TPB) {
        int s = cnt[0][e] + cnt[2][e] + cnt[4][e] + cnt[6][e];
        atomicAdd(&g_counts[e], (float)s);
    }
}

// ---------------------------------------------------------------- k2: distances (round-12 version)
__global__ __launch_bounds__(K2_TPB) void k2_dist(const float4* __restrict__ x,
                                                  const int* __restrict__ t32,
                                                  int n) {
    __shared__ __align__(16) float ctr[C_NUM * DIM];
    __shared__ float wsum[K2_WPB];

    const int tid  = threadIdx.x;
    const int warp = tid >> 5;
    const int lane = tid & 31;
    const int sh   = g_tmode;

    for (int e = tid; e < C_NUM * DIM; e += K2_TPB)
        ctr[e] = g_sums[e] / g_counts[e >> 7];
    __syncthreads();

    const int W  = K2_GRID * K2_WPB;
    const int gw = blockIdx.x * K2_WPB + warp;
    float lsum = 0.f;

    for (int r = gw; r < n; r += 4 * W) {
        const int rv0 = n - 1 - r;
        const int rv1 = rv0 - W, rv2 = rv0 - 2 * W, rv3 = rv0 - 3 * W;
        const bool ok1 = (r + W) < n, ok2 = (r + 2 * W) < n, ok3 = (r + 3 * W) < n;

        int t0, t1 = 0, t2 = 0, t3 = 0;
        float4 v0, v1, v2, v3;
        t0 = load_tgt(t32, rv0, sh); v0 = x[rv0 * 32 + lane];
        if (ok1) { t1 = load_tgt(t32, rv1, sh); v1 = x[rv1 * 32 + lane]; }
        if (ok2) { t2 = load_tgt(t32, rv2, sh); v2 = x[rv2 * 32 + lane]; }
        if (ok3) { t3 = load_tgt(t32, rv3, sh); v3 = x[rv3 * 32 + lane]; }

        float s0, s1 = 0.f, s2 = 0.f, s3 = 0.f;
        {
            float4 c = ((const float4*)(ctr + t0 * DIM))[lane];
            float dx = v0.x - c.x, dy = v0.y - c.y, dz = v0.z - c.z, dw = v0.w - c.w;
            s0 = dx * dx + dy * dy + dz * dz + dw * dw;
        }
        if (ok1) {
            float4 c = ((const float4*)(ctr + t1 * DIM))[lane];
            float dx = v1.x - c.x, dy = v1.y - c.y, dz = v1.z - c.z, dw = v1.w - c.w;
            s1 = dx * dx + dy * dy + dz * dz + dw * dw;
        }
        if (ok2) {
            float4 c = ((const float4*)(ctr + t2 * DIM))[lane];
            float dx = v2.x - c.x, dy = v2.y - c.y, dz = v2.z - c.z, dw = v2.w - c.w;
            s2 = dx * dx + dy * dy + dz * dz + dw * dw;
        }
        if (ok3) {
            float4 c = ((const float4*)(ctr + t3 * DIM))[lane];
            float dx = v3.x - c.x, dy = v3.y - c.y, dz = v3.z - c.z, dw = v3.w - c.w;
            s3 = dx * dx + dy * dy + dz * dz + dw * dw;
        }

        #pragma unroll
        for (int off = 16; off > 0; off >>= 1) {
            s0 += __shfl_xor_sync(0xffffffffu, s0, off);
            s1 += __shfl_xor_sync(0xffffffffu, s1, off);
            s2 += __shfl_xor_sync(0xffffffffu, s2, off);
            s3 += __shfl_xor_sync(0xffffffffu, s3, off);
        }
        if (lane == 0) {
            lsum += sqrtf(s0);
            if (ok1) lsum += sqrtf(s1);
            if (ok2) lsum += sqrtf(s2);
            if (ok3) lsum += sqrtf(s3);
        }
    }

    if (lane == 0) wsum[warp] = lsum;
    __syncthreads();
    if (tid == 0) {
        float s = 0.f;
        #pragma unroll
        for (int w = 0; w < K2_WPB; w++) s += wsum[w];
        atomicAdd(&g_loss, s);
    }
}

// ---------------------------------------------------------------- k3: finalize
__global__ void k3_final(float* __restrict__ out, int n) {
    if (threadIdx.x == 0) out[0] = g_loss / (float)n;
}

// ---------------------------------------------------------------- launch
extern "C" void kernel_launch(void* const* d_in, const int* in_sizes, int n_in,
                              void* d_out, int out_size) {
    const void* a = d_in[0];
    const void* b = d_in[1];
    const float* x;
    const int*   tgt;
    int n;
    if (in_sizes[0] >= in_sizes[1]) {
        x = (const float*)a;  tgt = (const int*)b;  n = in_sizes[1];
    } else {
        x = (const float*)b;  tgt = (const int*)a;  n = in_sizes[0];
    }
    float* out = (float*)d_out;

    k0_zero_probe<<<1, 256>>>(tgt, n);
    k1_segsum<<<K1_GRID, K1_TPB>>>((const float2*)x, tgt, n);
    k2_dist<<<K2_GRID, K2_TPB>>>((const float4*)x, tgt, n);
    k3_final<<<1, 32>>>(out, n);
}

// round 16
// speedup vs baseline: 1.3028x; 1.0224x over previous
#include <cuda_runtime.h>

#define C_NUM 19
#define DIM   128

// ---- k1: round-12 config (known good): 4 warps, per-warp [19][128] acc ----
#define K1_WPB   4
#define K1_TPB   (K1_WPB * 32)
#define K1_GRID  740            // 5 blocks/SM * 148 SMs -> single wave
#define K1_UNROLL 8

// ---- k2: round-12 config (known good) ----
#define K2_WPB   8
#define K2_TPB   (K2_WPB * 32)  // 256 threads
#define K2_GRID  888            // 6 blocks/SM * 148 SMs; 48 warps/SM

// Persistent scratch: zero-initialized at module load; the LAST exiting block
// of k2 resets everything at the end of each run, so every graph replay starts
// from zeros deterministically.
__device__ float    g_sums[C_NUM * DIM];
__device__ float    g_counts[C_NUM];
__device__ float    g_loss;
__device__ unsigned g_done;

__device__ __forceinline__ int clamp_c(int t) {
    return t < 0 ? 0 : (t >= C_NUM ? C_NUM - 1 : t);
}

// Per-block inline dtype probe: view targets as int32. int64 labels in [0,19)
// -> every odd 32-bit word is 0 (LE high word). For genuine int32 labels
// P(all odd words zero) ~ (1/19)^64 ~ 0. Costs one 512B L2-broadcast read.
__device__ __forceinline__ int probe_tmode(const int* __restrict__ t32, int n, int lane) {
    int m = n < 128 ? n : 128;
    int oddnz = 0;
    for (int i = lane; i < m; i += 32)
        if (t32[2 * i + 1] != 0) oddnz = 1;
    unsigned any = __ballot_sync(0xffffffffu, oddnz);
    return (any == 0u) ? 1 : 0;
}

// ---------------------------------------------------------------- k1: per-class sums
// One warp per row (32 lanes x float4 = 128 floats, coalesced 512B/row).
// Per-warp PRIVATE shared accumulator [19][128] -> no hot-loop atomics; lane l
// owns bytes [16l,16l+16) of each class row -> conflict-free LDS.128/STS.128 RMW.
// 8-row unroll, loads front-batched for MLP over the 577-cyc DRAM latency.
__global__ __launch_bounds__(K1_TPB) void k1_segsum(const float4* __restrict__ x,
                                                    const int* __restrict__ t32,
                                                    int n) {
    __shared__ __align__(16) float acc[K1_WPB][C_NUM * DIM];   // 38,912 B
    __shared__ int cnt[K1_WPB][C_NUM];
    __shared__ int s_sh;

    const int tid  = threadIdx.x;
    const int warp = tid >> 5;
    const int lane = tid & 31;

    if (warp == 0) {
        int tm = probe_tmode(t32, n, lane);
        if (lane == 0) s_sh = tm;
    }
    for (int e = tid; e < K1_WPB * C_NUM * DIM; e += K1_TPB) (&acc[0][0])[e] = 0.f;
    for (int e = tid; e < K1_WPB * C_NUM; e += K1_TPB) (&cnt[0][0])[e] = 0;
    __syncthreads();
    const int sh = s_sh;

    const int W  = K1_GRID * K1_WPB;
    const int gw = blockIdx.x * K1_WPB + warp;
    float* my = acc[warp];

    for (int r = gw; r < n; r += K1_UNROLL * W) {
        int    t[K1_UNROLL];
        float4 v[K1_UNROLL];
        bool   ok[K1_UNROLL];

        #pragma unroll
        for (int u = 0; u < K1_UNROLL; u++) {     // front-batched global loads (MLP)
            int ri = r + u * W;
            ok[u] = ri < n;
            if (ok[u]) { t[u] = clamp_c(t32[ri << sh]); v[u] = x[ri * 32 + lane]; }
        }

        #pragma unroll
        for (int u = 0; u < K1_UNROLL; u++) {
            if (ok[u]) {
                float4* p = (float4*)(my + t[u] * DIM) + lane;
                float4 a = *p;
                a.x += v[u].x; a.y += v[u].y; a.z += v[u].z; a.w += v[u].w;
                *p = a;
                if (lane == 0) cnt[warp][t[u]]++;
            }
        }
    }
    __syncthreads();

    // block-reduce 4 warp accumulators, flush with L2 atomics (2432 addrs, cheap)
    for (int e = tid; e < C_NUM * DIM; e += K1_TPB) {
        float s = acc[0][e] + acc[1][e] + acc[2][e] + acc[3][e];
        atomicAdd(&g_sums[e], s);
    }
    for (int e = tid; e < C_NUM; e += K1_TPB) {
        float s = (float)(cnt[0][e] + cnt[1][e] + cnt[2][e] + cnt[3][e]);
        atomicAdd(&g_counts[e], s);
    }
}

// ---------------------------------------------------------------- k2: distances + finalize + reset
// Rows traversed in REVERSE order (k1 streamed forward -> tail may be L2-resident).
// Last exiting block writes the output and resets all scratch for the next replay.
__global__ __launch_bounds__(K2_TPB) void k2_dist(const float4* __restrict__ x,
                                                  const int* __restrict__ t32,
                                                  float* __restrict__ out, int n) {
    __shared__ __align__(16) float ctr[C_NUM * DIM];   // 9,728 B
    __shared__ float wsum[K2_WPB];
    __shared__ int s_misc[2];                          // [0]=tmode, [1]=is-last-block

    const int tid  = threadIdx.x;
    const int warp = tid >> 5;
    const int lane = tid & 31;

    if (warp == 0) {
        int tm = probe_tmode(t32, n, lane);
        if (lane == 0) s_misc[0] = tm;
    }
    for (int e = tid; e < C_NUM * DIM; e += K2_TPB)
        ctr[e] = g_sums[e] / g_counts[e >> 7];   // e/128 -> class id
    __syncthreads();
    const int sh = s_misc[0];

    const int W  = K2_GRID * K2_WPB;
    const int gw = blockIdx.x * K2_WPB + warp;
    float lsum = 0.f;

    for (int r = gw; r < n; r += 4 * W) {
        const int rv0 = n - 1 - r;
        const int rv1 = rv0 - W, rv2 = rv0 - 2 * W, rv3 = rv0 - 3 * W;
        const bool ok1 = (r + W) < n, ok2 = (r + 2 * W) < n, ok3 = (r + 3 * W) < n;

        int t0, t1 = 0, t2 = 0, t3 = 0;
        float4 v0, v1, v2, v3;
        t0 = clamp_c(t32[rv0 << sh]); v0 = x[rv0 * 32 + lane];
        if (ok1) { t1 = clamp_c(t32[rv1 << sh]); v1 = x[rv1 * 32 + lane]; }
        if (ok2) { t2 = clamp_c(t32[rv2 << sh]); v2 = x[rv2 * 32 + lane]; }
        if (ok3) { t3 = clamp_c(t32[rv3 << sh]); v3 = x[rv3 * 32 + lane]; }

        float s0, s1 = 0.f, s2 = 0.f, s3 = 0.f;
        {
            float4 c = ((const float4*)(ctr + t0 * DIM))[lane];
            float dx = v0.x - c.x, dy = v0.y - c.y, dz = v0.z - c.z, dw = v0.w - c.w;
            s0 = dx * dx + dy * dy + dz * dz + dw * dw;
        }
        if (ok1) {
            float4 c = ((const float4*)(ctr + t1 * DIM))[lane];
            float dx = v1.x - c.x, dy = v1.y - c.y, dz = v1.z - c.z, dw = v1.w - c.w;
            s1 = dx * dx + dy * dy + dz * dz + dw * dw;
        }
        if (ok2) {
            float4 c = ((const float4*)(ctr + t2 * DIM))[lane];
            float dx = v2.x - c.x, dy = v2.y - c.y, dz = v2.z - c.z, dw = v2.w - c.w;
            s2 = dx * dx + dy * dy + dz * dz + dw * dw;
        }
        if (ok3) {
            float4 c = ((const float4*)(ctr + t3 * DIM))[lane];
            float dx = v3.x - c.x, dy = v3.y - c.y, dz = v3.z - c.z, dw = v3.w - c.w;
            s3 = dx * dx + dy * dy + dz * dz + dw * dw;
        }

        #pragma unroll
        for (int off = 16; off > 0; off >>= 1) {
            s0 += __shfl_xor_sync(0xffffffffu, s0, off);
            s1 += __shfl_xor_sync(0xffffffffu, s1, off);
            s2 += __shfl_xor_sync(0xffffffffu, s2, off);
            s3 += __shfl_xor_sync(0xffffffffu, s3, off);
        }
        if (lane == 0) {
            lsum += sqrtf(s0);
            if (ok1) lsum += sqrtf(s1);
            if (ok2) lsum += sqrtf(s2);
            if (ok3) lsum += sqrtf(s3);
        }
    }

    if (lane == 0) wsum[warp] = lsum;
    __syncthreads();
    if (tid == 0) {
        float s = 0.f;
        #pragma unroll
        for (int w = 0; w < K2_WPB; w++) s += wsum[w];
        atomicAdd(&g_loss, s);
        __threadfence();
        unsigned old = atomicAdd(&g_done, 1u);
        s_misc[1] = (old == K2_GRID - 1) ? 1 : 0;
    }
    __syncthreads();

    // Last exiting block: every other block has added to g_loss and finished
    // reading g_sums/g_counts (their reads precede their g_done increment).
    if (s_misc[1]) {
        if (tid == 0) {
            __threadfence();
            float total = atomicAdd(&g_loss, 0.f);   // L2-coherent read
            out[0] = total / (float)n;
        }
        // reset scratch so the next graph replay starts from zeros
        for (int e = tid; e < C_NUM * DIM; e += K2_TPB) g_sums[e] = 0.f;
        if (tid < C_NUM) g_counts[tid] = 0.f;
        if (tid == 0) { g_loss = 0.f; __threadfence(); g_done = 0u; }
    }
}

// ---------------------------------------------------------------- launch
extern "C" void kernel_launch(void* const* d_in, const int* in_sizes, int n_in,
                              void* d_out, int out_size) {
    // Resolve input ordering by element count: inputs has 128x the elements of targets.
    const void* a = d_in[0];
    const void* b = d_in[1];
    const float* x;
    const int*   tgt;
    int n;
    if (in_sizes[0] >= in_sizes[1]) {
        x = (const float*)a;  tgt = (const int*)b;  n = in_sizes[1];
    } else {
        x = (const float*)b;  tgt = (const int*)a;  n = in_sizes[0];
    }
    float* out = (float*)d_out;

    k1_segsum<<<K1_GRID, K1_TPB>>>((const float4*)x, tgt, n);
    k2_dist<<<K2_GRID, K2_TPB>>>((const float4*)x, tgt, out, n);
}

// round 17
// speedup vs baseline: 1.4349x; 1.1014x over previous
#include <cuda_runtime.h>

#define C_NUM 19
#define DIM   128

// ---- k1: round-12 config (known good, ~64% of HBM spec) ----
#define K1_WPB   4
#define K1_TPB   (K1_WPB * 32)
#define K1_GRID  740            // 5 blocks/SM * 148 SMs -> single wave
#define K1_UNROLL 8

// ---- k2: octet-per-row layout ----
#define K2_WPB   8
#define K2_TPB   (K2_WPB * 32)  // 256 threads
#define K2_GRID  888            // 6 blocks/SM target
#define K2_NW    (K2_GRID * K2_WPB)

// Persistent scratch: zero-initialized at module load; the LAST exiting block
// of k2 resets everything, so every graph replay starts from zeros.
__device__ float    g_sums[C_NUM * DIM];
__device__ float    g_counts[C_NUM];
__device__ float    g_loss;
__device__ unsigned g_done;

__device__ __forceinline__ int clamp_c(int t) {
    return t < 0 ? 0 : (t >= C_NUM ? C_NUM - 1 : t);
}

// Inline dtype probe: int64 labels in [0,19) -> every odd 32-bit word is 0.
__device__ __forceinline__ int probe_tmode(const int* __restrict__ t32, int n, int lane) {
    int m = n < 128 ? n : 128;
    int oddnz = 0;
    for (int i = lane; i < m; i += 32)
        if (t32[2 * i + 1] != 0) oddnz = 1;
    unsigned any = __ballot_sync(0xffffffffu, oddnz);
    return (any == 0u) ? 1 : 0;
}

// ---------------------------------------------------------------- k1: per-class sums
// One warp per row; per-warp PRIVATE [19][128] shared accumulator -> no hot-loop
// atomics, conflict-free LDS.128/STS.128 RMW; 8-row unroll, loads front-batched.
__global__ __launch_bounds__(K1_TPB) void k1_segsum(const float4* __restrict__ x,
                                                    const int* __restrict__ t32,
                                                    int n) {
    __shared__ __align__(16) float acc[K1_WPB][C_NUM * DIM];   // 38,912 B
    __shared__ int cnt[K1_WPB][C_NUM];
    __shared__ int s_sh;

    const int tid  = threadIdx.x;
    const int warp = tid >> 5;
    const int lane = tid & 31;

    if (warp == 0) {
        int tm = probe_tmode(t32, n, lane);
        if (lane == 0) s_sh = tm;
    }
    for (int e = tid; e < K1_WPB * C_NUM * DIM; e += K1_TPB) (&acc[0][0])[e] = 0.f;
    for (int e = tid; e < K1_WPB * C_NUM; e += K1_TPB) (&cnt[0][0])[e] = 0;
    __syncthreads();
    const int sh = s_sh;

    const int W  = K1_GRID * K1_WPB;
    const int gw = blockIdx.x * K1_WPB + warp;
    float* my = acc[warp];

    for (int r = gw; r < n; r += K1_UNROLL * W) {
        int    t[K1_UNROLL];
        float4 v[K1_UNROLL];
        bool   ok[K1_UNROLL];

        #pragma unroll
        for (int u = 0; u < K1_UNROLL; u++) {     // front-batched loads (MLP)
            int ri = r + u * W;
            ok[u] = ri < n;
            if (ok[u]) { t[u] = clamp_c(t32[ri << sh]); v[u] = x[ri * 32 + lane]; }
        }
        #pragma unroll
        for (int u = 0; u < K1_UNROLL; u++) {
            if (ok[u]) {
                float4* p = (float4*)(my + t[u] * DIM) + lane;
                float4 a = *p;
                a.x += v[u].x; a.y += v[u].y; a.z += v[u].z; a.w += v[u].w;
                *p = a;
                if (lane == 0) cnt[warp][t[u]]++;
            }
        }
    }
    __syncthreads();

    for (int e = tid; e < C_NUM * DIM; e += K1_TPB) {
        float s = acc[0][e] + acc[1][e] + acc[2][e] + acc[3][e];
        atomicAdd(&g_sums[e], s);
    }
    for (int e = tid; e < C_NUM; e += K1_TPB) {
        float s = (float)(cnt[0][e] + cnt[1][e] + cnt[2][e] + cnt[3][e]);
        atomicAdd(&g_counts[e], s);
    }
}

// ---------------------------------------------------------------- k2: distances
// Octet-per-row: warp handles 4 consecutive rows/iter; octet o (lanes 8o..8o+7)
// owns row r+o, each lane covers 16 floats (4 x float4, stride 8). Per 4 rows:
// 4 LDG.128 + 1 LDG.32 + 4 LDS.128 + 3 SHFL + 1 sqrt (vs 20 SHFL + 4 sqrt before).
// Reverse traversal (k1 streamed forward). Last block finalizes + resets scratch.
__global__ __launch_bounds__(K2_TPB) void k2_dist(const float4* __restrict__ x4,
                                                  const int* __restrict__ t32,
                                                  float* __restrict__ out, int n) {
    __shared__ __align__(16) float ctr[C_NUM * DIM];   // 9,728 B
    __shared__ float wsum[K2_WPB];
    __shared__ int s_misc[2];                          // [0]=tmode, [1]=is-last-block

    const int tid  = threadIdx.x;
    const int warp = tid >> 5;
    const int lane = tid & 31;
    const int oct  = lane >> 3;
    const int sub  = lane & 7;

    if (warp == 0) {
        int tm = probe_tmode(t32, n, lane);
        if (lane == 0) s_misc[0] = tm;
    }
    for (int e = tid; e < C_NUM * DIM; e += K2_TPB)
        ctr[e] = g_sums[e] / g_counts[e >> 7];
    __syncthreads();
    const int sh = s_misc[0];

    const int gw = blockIdx.x * K2_WPB + warp;
    float lsum = 0.f;   // per-lane; only sub==0 lanes accumulate sqrt values

    for (int r = gw * 4; r < n; r += K2_NW * 4) {
        // reverse traversal: map forward counter r to descending group base
        const int base = n - 4 - r;                    // may be <0 only if n%4 != 0
        const int row  = base + oct;
        const bool ok  = ((unsigned)row < (unsigned)n);
        const int rc   = ok ? row : 0;

        const int t = clamp_c(t32[rc << sh]);          // octet-uniform

        const float4* p = x4 + rc * 32 + sub;
        float4 a0 = p[0], a1 = p[8], a2 = p[16], a3 = p[24];

        const float4* cp = (const float4*)(ctr + t * DIM) + sub;
        float s;
        {
            float4 c = cp[0];
            float dx = a0.x - c.x, dy = a0.y - c.y, dz = a0.z - c.z, dw = a0.w - c.w;
            s = dx * dx + dy * dy + dz * dz + dw * dw;
        }
        {
            float4 c = cp[8];
            float dx = a1.x - c.x, dy = a1.y - c.y, dz = a1.z - c.z, dw = a1.w - c.w;
            s += dx * dx + dy * dy + dz * dz + dw * dw;
        }
        {
            float4 c = cp[16];
            float dx = a2.x - c.x, dy = a2.y - c.y, dz = a2.z - c.z, dw = a2.w - c.w;
            s += dx * dx + dy * dy + dz * dz + dw * dw;
        }
        {
            float4 c = cp[24];
            float dx = a3.x - c.x, dy = a3.y - c.y, dz = a3.z - c.z, dw = a3.w - c.w;
            s += dx * dx + dy * dy + dz * dz + dw * dw;
        }

        // reduce within octet: 3 shuffles cover all 4 rows simultaneously
        s += __shfl_xor_sync(0xffffffffu, s, 4);
        s += __shfl_xor_sync(0xffffffffu, s, 2);
        s += __shfl_xor_sync(0xffffffffu, s, 1);

        float sq = sqrtf(s);
        if (sub == 0 && ok) lsum += sq;
    }

    // final warp reduction of per-lane partials (once)
    #pragma unroll
    for (int off = 16; off > 0; off >>= 1)
        lsum += __shfl_xor_sync(0xffffffffu, lsum, off);

    if (lane == 0) wsum[warp] = lsum;
    __syncthreads();
    if (tid == 0) {
        float s = 0.f;
        #pragma unroll
        for (int w = 0; w < K2_WPB; w++) s += wsum[w];
        atomicAdd(&g_loss, s);
        __threadfence();
        unsigned old = atomicAdd(&g_done, 1u);
        s_misc[1] = (old == K2_GRID - 1) ? 1 : 0;
    }
    __syncthreads();

    // Last exiting block: finalize output, reset scratch for next replay.
    if (s_misc[1]) {
        if (tid == 0) {
            __threadfence();
            float total = atomicAdd(&g_loss, 0.f);     // L2-coherent read
            out[0] = total / (float)n;
        }
        for (int e = tid; e < C_NUM * DIM; e += K2_TPB) g_sums[e] = 0.f;
        if (tid < C_NUM) g_counts[tid] = 0.f;
        if (tid == 0) { g_loss = 0.f; __threadfence(); g_done = 0u; }
    }
}

// ---------------------------------------------------------------- launch
extern "C" void kernel_launch(void* const* d_in, const int* in_sizes, int n_in,
                              void* d_out, int out_size) {
    // Resolve input ordering by element count: inputs has 128x the elements of targets.
    const void* a = d_in[0];
    const void* b = d_in[1];
    const float* x;
    const int*   tgt;
    int n;
    if (in_sizes[0] >= in_sizes[1]) {
        x = (const float*)a;  tgt = (const int*)b;  n = in_sizes[1];
    } else {
        x = (const float*)b;  tgt = (const int*)a;  n = in_sizes[0];
    }
    float* out = (float*)d_out;

    k1_segsum<<<K1_GRID, K1_TPB>>>((const float4*)x, tgt, n);
    k2_dist<<<K2_GRID, K2_TPB>>>((const float4*)x, tgt, out, n);
}